// round 16
// baseline (speedup 1.0000x reference)
#include <cuda_runtime.h>

// Problem constants
#define B        8
#define IN_CH    64
#define OUT_CH   64
#define GROUPS   8
#define FPG      8
#define H        256
#define W        256
#define PLANE    (H * W)
#define REP_DIM  32

#define TILE     64
#define SSTRIDE  72      // padded smem row stride (float4-friendly)
#define SINT     4       // interior column base in S (left halo at col 3)
#define THREADS  256

// ---------------------------------------------------------------------------
// Fused kernel (R6 load frame, slim compute threads for 5 CTAs/SM):
//  - threads 0..71 compute the (b,g) dynamic weights (leaky_relu(rep.W))
//  - interior S: thread sums 8 channels of one float4 column (LDG.128 x8)
//  - compute: thread = 4 cols x 32 rows x 1 channel (kr: 9 regs),
//    window refill = 1 LDS.128 + 2 LDS.32 per row, STG.128 streaming.
// grid: (16 tiles, GROUPS, B), 256 threads, 64x64 tile.
// ---------------------------------------------------------------------------
__device__ __forceinline__ int reflect_idx(int i) {
    i = (i < 0) ? -i : i;
    return (i > H - 1) ? (2 * (H - 1) - i) : i;
}

__global__ __launch_bounds__(THREADS, 5)
void dyn_conv_kernel(const float* __restrict__ x,
                     const float* __restrict__ rep,
                     const float* __restrict__ Wm,
                     float* __restrict__ out) {
    const int b = blockIdx.z;
    const int g = blockIdx.y;
    const int ty = (blockIdx.x >> 2) * TILE;
    const int tx = (blockIdx.x & 3) * TILE;
    const int tid = threadIdx.x;

    __shared__ float S[66 * SSTRIDE];    // group-sum tile + halo
    __shared__ float k9s[FPG * 9];

    // ---- Dynamic weights: 72 dot-products of length 32 (threads 0..71) ----
    if (tid < FPG * 9) {
        const int f = (g * FPG) * 9 + tid;
        const float4* r4 = (const float4*)(rep + b * REP_DIM);
        const float4* w4 = (const float4*)(Wm + (size_t)f * REP_DIM);
        float s = 0.f;
#pragma unroll
        for (int i = 0; i < REP_DIM / 4; i++) {
            float4 rv = __ldg(&r4[i]);
            float4 wv = __ldg(&w4[i]);
            s = fmaf(rv.x, wv.x, s);
            s = fmaf(rv.y, wv.y, s);
            s = fmaf(rv.z, wv.z, s);
            s = fmaf(rv.w, wv.w, s);
        }
        k9s[tid] = (s > 0.f) ? s : 0.1f * s;
    }

    const float* xbase = x + ((size_t)(b * IN_CH + g * FPG)) * PLANE;

    // ---- Interior: 66 rows x 16 float4 (1056 tasks: 4 full + 32 tail) ----
#pragma unroll
    for (int it = 0; it < 4; it++) {
        int i = tid + it * THREADS;
        int row = i >> 4;
        int c4  = i & 15;
        int gy = reflect_idx(ty + row - 1);
        const float* p = xbase + gy * W + tx + c4 * 4;
        float4 s = make_float4(0.f, 0.f, 0.f, 0.f);
#pragma unroll
        for (int c = 0; c < FPG; c++) {
            float4 v = *(const float4*)(p + c * PLANE);
            s.x += v.x; s.y += v.y; s.z += v.z; s.w += v.w;
        }
        *(float4*)&S[row * SSTRIDE + SINT + c4 * 4] = s;
    }
    if (tid < 32) {
        int i = 1024 + tid;
        int row = i >> 4;
        int c4  = i & 15;
        int gy = reflect_idx(ty + row - 1);
        const float* p = xbase + gy * W + tx + c4 * 4;
        float4 s = make_float4(0.f, 0.f, 0.f, 0.f);
#pragma unroll
        for (int c = 0; c < FPG; c++) {
            float4 v = *(const float4*)(p + c * PLANE);
            s.x += v.x; s.y += v.y; s.z += v.z; s.w += v.w;
        }
        *(float4*)&S[row * SSTRIDE + SINT + c4 * 4] = s;
    }

    // ---- Halo columns: 66 rows x 2 sides, scalar 8-channel sums ----
    if (tid < 132) {
        int row  = tid >> 1;
        int side = tid & 1;
        int gy = reflect_idx(ty + row - 1);
        int gx = side ? reflect_idx(tx + 64) : reflect_idx(tx - 1);
        const float* p = xbase + gy * W + gx;
        float s = 0.f;
#pragma unroll
        for (int c = 0; c < FPG; c++) s += p[c * PLANE];
        S[row * SSTRIDE + (side ? (SINT + 64) : (SINT - 1))] = s;
    }
    __syncthreads();

    // ---- Compute: thread = (xq, ch, strip) -> 4 cols, 32 rows, 1 channel
    const int xq    = tid & 15;          // 0..15 -> cols xq*4..xq*4+3
    const int ch    = (tid >> 4) & 7;    // 0..7  -> output channel
    const int strip = tid >> 7;          // 0..1  -> rows strip*32..+31
    const int lx0   = xq * 4;
    const int y0    = strip * 32;

    float kr[9];
#pragma unroll
    for (int t = 0; t < 9; t++) kr[t] = k9s[ch * 9 + t];

    // Sliding 3-row window of 6 S values (S cols lx0+3 .. lx0+8).
    // Refill: 1 LDS.128 (cols lx0+4..lx0+7, 16B-aligned) + 2 LDS.32 edges.
    float w0[6], w1[6], w2[6];
    {
        const float* Sp = &S[y0 * SSTRIDE + lx0 + 3];
        w0[0] = Sp[0];
        float4 m = *(const float4*)(Sp + 1);
        w0[1] = m.x; w0[2] = m.y; w0[3] = m.z; w0[4] = m.w;
        w0[5] = Sp[5];
        Sp += SSTRIDE;
        w1[0] = Sp[0];
        m = *(const float4*)(Sp + 1);
        w1[1] = m.x; w1[2] = m.y; w1[3] = m.z; w1[4] = m.w;
        w1[5] = Sp[5];
    }

    float* op = out + ((size_t)(b * OUT_CH + g * FPG + ch)) * PLANE
                    + (ty + y0) * W + tx + lx0;

#pragma unroll 4
    for (int y = 0; y < 32; y++) {
        const float* Sp = &S[(y0 + y + 2) * SSTRIDE + lx0 + 3];
        w2[0] = Sp[0];
        float4 m = *(const float4*)(Sp + 1);
        w2[1] = m.x; w2[2] = m.y; w2[3] = m.z; w2[4] = m.w;
        w2[5] = Sp[5];

        float4 r;
        r.x = kr[0] * w0[0];          r.y = kr[0] * w0[1];
        r.z = kr[0] * w0[2];          r.w = kr[0] * w0[3];
        r.x = fmaf(kr[1], w0[1], r.x); r.y = fmaf(kr[1], w0[2], r.y);
        r.z = fmaf(kr[1], w0[3], r.z); r.w = fmaf(kr[1], w0[4], r.w);
        r.x = fmaf(kr[2], w0[2], r.x); r.y = fmaf(kr[2], w0[3], r.y);
        r.z = fmaf(kr[2], w0[4], r.z); r.w = fmaf(kr[2], w0[5], r.w);
        r.x = fmaf(kr[3], w1[0], r.x); r.y = fmaf(kr[3], w1[1], r.y);
        r.z = fmaf(kr[3], w1[2], r.z); r.w = fmaf(kr[3], w1[3], r.w);
        r.x = fmaf(kr[4], w1[1], r.x); r.y = fmaf(kr[4], w1[2], r.y);
        r.z = fmaf(kr[4], w1[3], r.z); r.w = fmaf(kr[4], w1[4], r.w);
        r.x = fmaf(kr[5], w1[2], r.x); r.y = fmaf(kr[5], w1[3], r.y);
        r.z = fmaf(kr[5], w1[4], r.z); r.w = fmaf(kr[5], w1[5], r.w);
        r.x = fmaf(kr[6], w2[0], r.x); r.y = fmaf(kr[6], w2[1], r.y);
        r.z = fmaf(kr[6], w2[2], r.z); r.w = fmaf(kr[6], w2[3], r.w);
        r.x = fmaf(kr[7], w2[1], r.x); r.y = fmaf(kr[7], w2[2], r.y);
        r.z = fmaf(kr[7], w2[3], r.z); r.w = fmaf(kr[7], w2[4], r.w);
        r.x = fmaf(kr[8], w2[2], r.x); r.y = fmaf(kr[8], w2[3], r.y);
        r.z = fmaf(kr[8], w2[4], r.z); r.w = fmaf(kr[8], w2[5], r.w);
        __stcs((float4*)op, r);

        op += W;
#pragma unroll
        for (int j = 0; j < 6; j++) { w0[j] = w1[j]; w1[j] = w2[j]; }
    }
}

// ---------------------------------------------------------------------------
// Launch
// ---------------------------------------------------------------------------
extern "C" void kernel_launch(void* const* d_in, const int* in_sizes, int n_in,
                              void* d_out, int out_size) {
    const float* x   = (const float*)d_in[0];   // [8, 64, 256, 256]
    const float* rep = (const float*)d_in[1];   // [8, 32]
    const float* Wm  = (const float*)d_in[2];   // [576, 32]
    float* out = (float*)d_out;                 // [8, 64, 256, 256]

    (void)in_sizes; (void)n_in; (void)out_size;

    dim3 grid(16, GROUPS, B);   // single 64x64 tile per CTA
    dyn_conv_kernel<<<grid, THREADS>>>(x, rep, Wm, out);
}